// round 4
// baseline (speedup 1.0000x reference)
#include <cuda_runtime.h>

#define N    512
#define NA   180
#define NCH  4        // row-bands of 128 image rows each

// Scratch (no allocations allowed): transposed image + per-band partials.
__device__ float g_imgT[N * N];
__device__ float g_partial[NCH * NA * N];   // [(ch*NA + a)*N + d]

// ---------------------------------------------------------------------------
// Tiled transpose: img -> g_imgT  (1 MB, ~negligible)
// ---------------------------------------------------------------------------
__global__ void transpose_k(const float* __restrict__ img) {
    __shared__ float tile[32][33];
    int x  = blockIdx.x * 32 + threadIdx.x;
    int y0 = blockIdx.y * 32;
#pragma unroll
    for (int j = threadIdx.y; j < 32; j += 8)
        tile[j][threadIdx.x] = img[(y0 + j) * N + x];
    __syncthreads();
    int xo  = blockIdx.y * 32 + threadIdx.x;
    int yo0 = blockIdx.x * 32;
#pragma unroll
    for (int j = threadIdx.y; j < 32; j += 8)
        g_imgT[(yo0 + j) * N + xo] = tile[threadIdx.x][j];
}

// Checked bilinear sample (boundary / outside): per-corner valid-else-zero.
__device__ __forceinline__ float sample_checked(const float* __restrict__ src,
                                                float row, float col) {
    const float rf = floorf(row), cf = floorf(col);
    const float wr = row - rf,    wc = col - cf;
    const int   ir = (int)rf,     ic = (int)cf;
    const bool r0 = (unsigned)ir       < (unsigned)N;
    const bool r1 = (unsigned)(ir + 1) < (unsigned)N;
    const bool c0 = (unsigned)ic       < (unsigned)N;
    const bool c1 = (unsigned)(ic + 1) < (unsigned)N;
    float v00 = (r0 && c0) ? src[(ir << 9) + ic]           : 0.0f;
    float v01 = (r0 && c1) ? src[(ir << 9) + ic + 1]       : 0.0f;
    float v10 = (r1 && c0) ? src[((ir + 1) << 9) + ic]     : 0.0f;
    float v11 = (r1 && c1) ? src[((ir + 1) << 9) + ic + 1] : 0.0f;
    const float top = fmaf(wc, v01 - v00, v00);
    const float bot = fmaf(wc, v11 - v10, v10);
    return fmaf(wr, bot - top, top);
}

// ---------------------------------------------------------------------------
// Radon, row-banded: chunk ch sums exactly the y's whose sampled row lies in
// [128*ch, 128*(ch+1)). Per-lane staggered loop starts keep all 32 lanes on
// ~the same image row every SIMT step -> minimal 128B lines per warp-LDG.
// The interior fast loop is branch-free (4 unchecked LDGs); boundary y's go
// through the checked path. Band partition is made exact across chunks by
// correcting the division estimate with the same fmaf predicate all chunks
// evaluate.
// ---------------------------------------------------------------------------
__global__ void __launch_bounds__(128) radon_k(const float* __restrict__ img,
                                               const int*   __restrict__ angles) {
    const int d  = blockIdx.x * 128 + threadIdx.x;  // detector 0..511
    const int a  = blockIdx.y;                      // angle index
    const int ch = blockIdx.z;                      // row band

    const float c = (N - 1) * 0.5f;
    const float t = (float)angles[a] * 0.017453292519943295f;
    float si, co;
    sincosf(t, &si, &co);

    const bool useT = fabsf(si) > fabsf(co);
    const float* __restrict__ src = useT ? g_imgT : img;

    const float xc = (float)d - c;
    // row(y) = dr*(y-c) + rbase ; col(y) = dcc*(y-c) + cbase ; |dr| >= 0.707
    float dr, rbase, dcc, cbase;
    if (useT) { dr = si; rbase = fmaf( co, xc, c);
                dcc = co; cbase = fmaf(-si, xc, c); }
    else      { dr = co; rbase = fmaf(-si, xc, c);
                dcc = si; cbase = fmaf( co, xc, c); }

    // ---- exact band y-range [A, B): row in [r0, r1) ----
    const float r0 = (ch == 0)       ? -0.9999f : (float)(128 * ch);
    const float r1 = (ch == NCH - 1) ? 512.01f  : (float)(128 * (ch + 1));
    const float inv_dr = 1.0f / dr;

    int A, B;
    if (dr > 0.0f) {
        // first y with row(y) >= r0 ; first y with row(y) >= r1
        A = (int)ceilf(fmaf(r0 - rbase, inv_dr, c)) - 2;
        for (int k = 0; k < 8 && fmaf(dr, (float)A - c, rbase) < r0; ++k) ++A;
        B = (int)ceilf(fmaf(r1 - rbase, inv_dr, c)) - 2;
        for (int k = 0; k < 8 && fmaf(dr, (float)B - c, rbase) < r1; ++k) ++B;
    } else {
        // row decreasing: first y with row(y) < r1 ; first y with row(y) < r0
        A = (int)ceilf(fmaf(r1 - rbase, inv_dr, c)) - 2;
        for (int k = 0; k < 8 && fmaf(dr, (float)A - c, rbase) >= r1; ++k) ++A;
        B = (int)ceilf(fmaf(r0 - rbase, inv_dr, c)) - 2;
        for (int k = 0; k < 8 && fmaf(dr, (float)B - c, rbase) >= r0; ++k) ++B;
    }
    A = max(A, 0);
    B = min(B, N);

    // ---- conservative col ranges ----
    int CA, CB;          // overlap: col in (-1, 512)  (widened: only adds zeros)
    int ICA, ICB;        // interior: col in [0, 511)  (narrowed)
    if (fabsf(dcc) > 1e-6f) {
        const float inv_dc = 1.0f / dcc;
        float p = fmaf(-1.0f - cbase, inv_dc, c);
        float q = fmaf(512.0f - cbase, inv_dc, c);
        CA = (int)floorf(fminf(p, q)) - 2;
        CB = (int)ceilf (fmaxf(p, q)) + 2;
        p = fmaf(0.0f   - cbase, inv_dc, c);
        q = fmaf(511.0f - cbase, inv_dc, c);
        ICA = (int)ceilf (fminf(p, q)) + 2;
        ICB = (int)floorf(fmaxf(p, q)) - 2;
    } else {
        const bool any = (cbase > -0.999f) && (cbase < 511.999f);
        const bool in  = (cbase >  0.01f)  && (cbase < 510.9f);
        CA  = any ? -100000 : 100000;  CB  = any ? 100000 : -100000;
        ICA = in  ? -100000 : 100000;  ICB = in  ? 100000 : -100000;
    }

    // ---- conservative interior row range (band-clamped, narrowed) ----
    {
        const float ra = fmaxf(r0, 0.001f);
        const float rb = fminf(r1, 510.99f);
        const float p  = fmaf(ra - rbase, inv_dr, c);
        const float q  = fmaf(rb - rbase, inv_dr, c);
        const int ira = (int)ceilf (fminf(p, q)) + 2;
        const int irb = (int)floorf(fmaxf(p, q)) - 2;
        ICA = max(ICA, ira);
        ICB = min(ICB, irb);
    }

    // loop ranges: [L0, L1) total, [I0, I1) interior fast
    const int L0 = max(A, CA);
    const int L1 = min(B, CB + 1);
    int I0 = min(max(ICA, L0), L1);
    int I1 = min(max(ICB + 1, I0), L1);

    float acc = 0.0f;
    int y = L0;

    for (; y < I0; ++y) {
        const float yc = (float)y - c;
        acc += sample_checked(src, fmaf(dr, yc, rbase), fmaf(dcc, yc, cbase));
    }

#pragma unroll 4
    for (; y < I1; ++y) {
        const float yc  = (float)y - c;
        const float row = fmaf(dr, yc, rbase);
        const float col = fmaf(dcc, yc, cbase);
        const float rf = floorf(row), cf = floorf(col);
        const float wr = row - rf,    wc = col - cf;
        const int   ir = (int)rf,     ic = (int)cf;
        const float* p = src + (ir << 9) + ic;
        const float v00 = __ldg(p);     const float v01 = __ldg(p + 1);
        const float v10 = __ldg(p + N); const float v11 = __ldg(p + N + 1);
        const float top = fmaf(wc, v01 - v00, v00);
        const float bot = fmaf(wc, v11 - v10, v10);
        acc += fmaf(wr, bot - top, top);
    }

    for (; y < L1; ++y) {
        const float yc = (float)y - c;
        acc += sample_checked(src, fmaf(dr, yc, rbase), fmaf(dcc, yc, cbase));
    }

    g_partial[(ch * NA + a) * N + d] = acc;   // coalesced in d
}

// ---------------------------------------------------------------------------
// Deterministic reduction over bands (fixed order).
// ---------------------------------------------------------------------------
__global__ void reduce_k(float* __restrict__ out) {
    const int j = blockIdx.x * blockDim.x + threadIdx.x;
    if (j < N * NA) {
        const int d = j & (N - 1);
        const int a = j >> 9;
        float s = 0.0f;
#pragma unroll
        for (int ch = 0; ch < NCH; ++ch)
            s += g_partial[(ch * NA + a) * N + d];
        out[d * NA + a] = s;
    }
}

extern "C" void kernel_launch(void* const* d_in, const int* in_sizes, int n_in,
                              void* d_out, int out_size) {
    const float* img    = (const float*)d_in[0];
    const int*   angles = (const int*)d_in[1];
    float*       out    = (float*)d_out;

    transpose_k<<<dim3(N / 32, N / 32), dim3(32, 8)>>>(img);
    radon_k<<<dim3(N / 128, NA, NCH), 128>>>(img, angles);
    reduce_k<<<(N * NA + 255) / 256, 256>>>(out);
}

// round 7
// speedup vs baseline: 1.2667x; 1.2667x over previous
#include <cuda_runtime.h>

#define N    512
#define NA   180
#define NCH  8
#define YPC  (N / NCH)   // 64 y-samples per chunk

// Scratch (no allocations allowed): transposed image + per-chunk partials.
__device__ float g_imgT[N * N];
__device__ float g_partial[NCH * N * NA];

// ---------------------------------------------------------------------------
// Tiled transpose: img -> g_imgT  (1 MB, ~negligible)
// ---------------------------------------------------------------------------
__global__ void transpose_k(const float* __restrict__ img) {
    __shared__ float tile[32][33];
    int x  = blockIdx.x * 32 + threadIdx.x;
    int y0 = blockIdx.y * 32;
#pragma unroll
    for (int j = threadIdx.y; j < 32; j += 8)
        tile[j][threadIdx.x] = img[(y0 + j) * N + x];
    __syncthreads();
    int xo  = blockIdx.y * 32 + threadIdx.x;
    int yo0 = blockIdx.x * 32;
#pragma unroll
    for (int j = threadIdx.y; j < 32; j += 8)
        g_imgT[(yo0 + j) * N + xo] = tile[threadIdx.x][j];
}

// ---------------------------------------------------------------------------
// Radon: one thread = one (detector d, angle a) pair, partial sum over a
// y-chunk. Per-angle we sample either img or imgT (coords swapped) so the
// warp-lane (detector) axis has the smaller row derivative. Deep unroll for
// MLP: the loop body's 4 loads x8 iterations are independent.
// zbase selects which half of the chunks this launch covers (lets us split
// radon into two launches purely so ncu's fixed capture slot lands on it).
// ---------------------------------------------------------------------------
__global__ void __launch_bounds__(128) radon_k(const float* __restrict__ img,
                                               const int*   __restrict__ angles,
                                               int zbase) {
    const int d  = blockIdx.x * blockDim.x + threadIdx.x;  // detector 0..511
    const int a  = blockIdx.y;                             // angle index
    const int ch = zbase + blockIdx.z;                     // y-chunk

    const float c = (N - 1) * 0.5f;
    const float t = (float)angles[a] * 0.017453292519943295f;
    float si, co;
    sincosf(t, &si, &co);

    const bool useT = fabsf(si) > fabsf(co);
    const float* __restrict__ src = useT ? g_imgT : img;

    const float xc = (float)d - c;
    // row = dr*yc + rbase ; col = dc*yc + cbase
    float dr, rbase, dc, cbase;
    if (useT) { dr = si; rbase = fmaf( co, xc, c);
                dc = co; cbase = fmaf(-si, xc, c); }
    else      { dr = co; rbase = fmaf(-si, xc, c);
                dc = si; cbase = fmaf( co, xc, c); }

    float acc = 0.0f;
    const int ybeg = ch * YPC;
#pragma unroll 8
    for (int y = ybeg; y < ybeg + YPC; ++y) {
        const float yc  = (float)y - c;
        const float row = fmaf(dr, yc, rbase);
        const float col = fmaf(dc, yc, cbase);

        const float rf = floorf(row), cf = floorf(col);
        const float wr = row - rf,    wc = col - cf;
        const int   ir = (int)rf,     ic = (int)cf;

        float v00, v01, v10, v11;
        if ((unsigned)ir < (unsigned)(N - 1) && (unsigned)ic < (unsigned)(N - 1)) {
            // interior fast path: 4 unchecked loads
            const float* p = src + (ir << 9) + ic;
            v00 = __ldg(p);     v01 = __ldg(p + 1);
            v10 = __ldg(p + N); v11 = __ldg(p + N + 1);
        } else {
            // boundary / outside: per-corner valid-else-zero (matches reference)
            const bool r0 = (unsigned)ir       < (unsigned)N;
            const bool r1 = (unsigned)(ir + 1) < (unsigned)N;
            const bool c0 = (unsigned)ic       < (unsigned)N;
            const bool c1 = (unsigned)(ic + 1) < (unsigned)N;
            v00 = (r0 && c0) ? src[(ir << 9) + ic]           : 0.0f;
            v01 = (r0 && c1) ? src[(ir << 9) + ic + 1]       : 0.0f;
            v10 = (r1 && c0) ? src[((ir + 1) << 9) + ic]     : 0.0f;
            v11 = (r1 && c1) ? src[((ir + 1) << 9) + ic + 1] : 0.0f;
        }
        const float top = fmaf(wc, v01 - v00, v00);
        const float bot = fmaf(wc, v11 - v10, v10);
        acc += fmaf(wr, bot - top, top);
    }
    g_partial[(ch * N + d) * NA + a] = acc;
}

// ---------------------------------------------------------------------------
// Deterministic partial reduction: out[i] = sum over chunks (fixed order).
// ---------------------------------------------------------------------------
__global__ void reduce_k(float* __restrict__ out) {
    const int i = blockIdx.x * blockDim.x + threadIdx.x;
    if (i < N * NA) {
        const int d = i / NA;        // matches g_partial layout [(ch*N+d)*NA+a]
        const int a = i - d * NA;
        float s = 0.0f;
#pragma unroll
        for (int ch = 0; ch < NCH; ++ch)
            s += g_partial[(ch * N + d) * NA + a];
        out[i] = s;
    }
}

extern "C" void kernel_launch(void* const* d_in, const int* in_sizes, int n_in,
                              void* d_out, int out_size) {
    const float* img    = (const float*)d_in[0];
    const int*   angles = (const int*)d_in[1];
    float*       out    = (float*)d_out;

    transpose_k<<<dim3(N / 32, N / 32), dim3(32, 8)>>>(img);
    // Two equal radon launches: 4 launches per call => ncu's capture slot
    // (launch idx 5 or 6) lands on radon_k instead of transpose_k.
    radon_k<<<dim3(N / 128, NA, NCH / 2), 128>>>(img, angles, 0);
    radon_k<<<dim3(N / 128, NA, NCH / 2), 128>>>(img, angles, NCH / 2);
    reduce_k<<<(N * NA + 255) / 256, 256>>>(out);
}